// round 1
// baseline (speedup 1.0000x reference)
#include <cuda_runtime.h>
#include <cstdint>
#include <float.h>

#define FRAME   160
#define HOP     256
#define MIN_LAG 40
#define MAX_LAG 160
#define NBATCH  16

// ---- f32x2 helpers (Blackwell packed fp32 pipe; only reachable via PTX) ----
__device__ __forceinline__ unsigned long long pk2(float a, float b) {
    unsigned long long r;
    asm("mov.b64 %0, {%1, %2};"
        : "=l"(r) : "r"(__float_as_uint(a)), "r"(__float_as_uint(b)));
    return r;
}
__device__ __forceinline__ void upk2(unsigned long long v, float& a, float& b) {
    unsigned int lo, hi;
    asm("mov.b64 {%0, %1}, %2;" : "=r"(lo), "=r"(hi) : "l"(v));
    a = __uint_as_float(lo);
    b = __uint_as_float(hi);
}
__device__ __forceinline__ unsigned long long fma2(unsigned long long a,
                                                   unsigned long long b,
                                                   unsigned long long c) {
    unsigned long long d;
    asm("fma.rn.f32x2 %0, %1, %2, %3;" : "=l"(d) : "l"(a), "l"(b), "l"(c));
    return d;
}

// One warp handles TWO frames (A = even, B = odd), packed as f32x2 lanes.
// Each lane owns 4 consecutive lags l0..l0+3 (l0 = 40 + 4*lane, lanes 0..29).
// Sliding 8-entry register window over the zero-padded frame gives
// 16 f32x2-FMAs per 4 LDS.128 (all conflict-free: lane stride = 16B).
__global__ __launch_bounds__(256, 4)
void pitch_kernel(const float* __restrict__ audio,
                  float* __restrict__ out,
                  int S, int T, int total_frames) {
    // per-warp, per-frame padded buffer: [0..127] zeros, [128..287] = centered frame
    __shared__ __align__(16) float sbuf[8][2][288];

    const int warp = threadIdx.x >> 5;
    const int lane = threadIdx.x & 31;
    const int g0   = (blockIdx.x * 8 + warp) * 2;   // first frame id of this warp
    if (g0 + 1 >= total_frames + 1) return;          // whole-warp guard (pairs exact here)

    const int batch = g0 / T;
    const int f0    = g0 - batch * T;
    const float* base = audio + (size_t)batch * S;

    float* bufA = sbuf[warp][0];
    float* bufB = sbuf[warp][1];

    // ---- load, mean-center, silence flag, stage to shared ----
    float silent0 = 0.f, silent1 = 0.f;
    #pragma unroll
    for (int s = 0; s < 2; ++s) {
        const float* gp = base + (size_t)(f0 + s) * HOP;
        float v[5];
        #pragma unroll
        for (int i = 0; i < 5; ++i) v[i] = gp[lane + 32 * i];   // 160 = 5*32 exact
        float sum = v[0] + v[1] + v[2] + v[3] + v[4];
        #pragma unroll
        for (int off = 16; off; off >>= 1)
            sum += __shfl_xor_sync(0xffffffffu, sum, off);
        const float mean = sum / 160.0f;

        float* buf = s ? bufB : bufA;
        float ma = 0.f;
        #pragma unroll
        for (int i = 0; i < 5; ++i) {
            float c = v[i] - mean;
            buf[128 + lane + 32 * i] = c;
            ma = fmaxf(ma, fabsf(c));
        }
        #pragma unroll
        for (int off = 16; off; off >>= 1)
            ma = fmaxf(ma, __shfl_xor_sync(0xffffffffu, ma, off));
        // zero pad region [0,128)
        #pragma unroll
        for (int i = 0; i < 4; ++i) buf[lane + 32 * i] = 0.f;

        if (s == 0) silent0 = (ma < 1e-8f) ? 1.f : 0.f;
        else        silent1 = (ma < 1e-8f) ? 1.f : 0.f;
    }
    __syncwarp();

    // ---- windowed self-convolution: c[l] = sum_n x[n] * xpad[l-n] ----
    const int tl = (lane < 30) ? lane : 29;     // lanes 30,31 duplicate lane 29 (discarded)
    const int l0 = MIN_LAG + 4 * tl;

    unsigned long long acc0 = 0ull, acc1 = 0ull, acc2 = 0ull, acc3 = 0ull;
    unsigned long long w[8];
    {   // init window: w[k] = xpad[l0-4+k]  (buf index 128+l0-4, 16B aligned)
        const float4 a0 = *(const float4*)&bufA[128 + l0 - 4];
        const float4 a1 = *(const float4*)&bufA[128 + l0];
        const float4 b0 = *(const float4*)&bufB[128 + l0 - 4];
        const float4 b1 = *(const float4*)&bufB[128 + l0];
        w[0] = pk2(a0.x, b0.x); w[1] = pk2(a0.y, b0.y);
        w[2] = pk2(a0.z, b0.z); w[3] = pk2(a0.w, b0.w);
        w[4] = pk2(a1.x, b1.x); w[5] = pk2(a1.y, b1.y);
        w[6] = pk2(a1.z, b1.z); w[7] = pk2(a1.w, b1.w);
    }

    #pragma unroll 4
    for (int n0 = 0; n0 < FRAME; n0 += 4) {
        const float4 xa = *(const float4*)&bufA[128 + n0];      // broadcast
        const float4 xb = *(const float4*)&bufB[128 + n0];
        const unsigned long long x0 = pk2(xa.x, xb.x);
        const unsigned long long x1 = pk2(xa.y, xb.y);
        const unsigned long long x2 = pk2(xa.z, xb.z);
        const unsigned long long x3 = pk2(xa.w, xb.w);

        // n = n0+u contributes x[n] * xpad[l0+j-n] = x[n] * w[4+j-u]
        acc0 = fma2(x0, w[4], acc0); acc1 = fma2(x0, w[5], acc1);
        acc2 = fma2(x0, w[6], acc2); acc3 = fma2(x0, w[7], acc3);
        acc0 = fma2(x1, w[3], acc0); acc1 = fma2(x1, w[4], acc1);
        acc2 = fma2(x1, w[5], acc2); acc3 = fma2(x1, w[6], acc3);
        acc0 = fma2(x2, w[2], acc0); acc1 = fma2(x2, w[3], acc1);
        acc2 = fma2(x2, w[4], acc2); acc3 = fma2(x2, w[5], acc3);
        acc0 = fma2(x3, w[1], acc0); acc1 = fma2(x3, w[2], acc1);
        acc2 = fma2(x3, w[3], acc2); acc3 = fma2(x3, w[4], acc3);

        // shift window up by 4 and refill low half for next chunk
        // next chunk needs w'[k] = xpad[l0-n0-8+k]  (reads stay >= buf[4])
        const float4 ra = *(const float4*)&bufA[128 + l0 - n0 - 8];
        const float4 rb = *(const float4*)&bufB[128 + l0 - n0 - 8];
        w[7] = w[3]; w[6] = w[2]; w[5] = w[1]; w[4] = w[0];
        w[0] = pk2(ra.x, rb.x); w[1] = pk2(ra.y, rb.y);
        w[2] = pk2(ra.z, rb.z); w[3] = pk2(ra.w, rb.w);
    }

    // ---- per-lane first-max, then warp argmax (tie -> smaller lag) ----
    float cA[4], cB[4];
    upk2(acc0, cA[0], cB[0]); upk2(acc1, cA[1], cB[1]);
    upk2(acc2, cA[2], cB[2]); upk2(acc3, cA[3], cB[3]);

    float bA = -FLT_MAX, bB = -FLT_MAX;
    int   lA = 0x7fffffff, lB = 0x7fffffff;
    if (lane < 30) {
        #pragma unroll
        for (int j = 0; j < 4; ++j) {
            const int l = l0 + j;
            if (cA[j] > bA) { bA = cA[j]; lA = l; }
            if (cB[j] > bB) { bB = cB[j]; lB = l; }
        }
    }
    #pragma unroll
    for (int off = 16; off; off >>= 1) {
        float vA = __shfl_xor_sync(0xffffffffu, bA, off);
        int   iA = __shfl_xor_sync(0xffffffffu, lA, off);
        if (vA > bA || (vA == bA && iA < lA)) { bA = vA; lA = iA; }
        float vB = __shfl_xor_sync(0xffffffffu, bB, off);
        int   iB = __shfl_xor_sync(0xffffffffu, lB, off);
        if (vB > bB || (vB == bB && iB < lB)) { bB = vB; lB = iB; }
    }

    if (lane == 0) {
        out[g0]     = (silent0 != 0.f) ? 0.f : 16000.0f / (float)lA;
        out[g0 + 1] = (silent1 != 0.f) ? 0.f : 16000.0f / (float)lB;
    }
}

extern "C" void kernel_launch(void* const* d_in, const int* in_sizes, int n_in,
                              void* d_out, int out_size) {
    const float* audio = (const float*)d_in[0];
    float* out = (float*)d_out;

    const int total = in_sizes[0];              // 16 * 1048576
    const int B = NBATCH;
    const int S = total / B;                    // 1048576
    const int T = (S - FRAME) / HOP + 1;        // 4096
    const int frames = B * T;                   // 65536 == out_size
    const int pairs  = frames / 2;              // 32768
    const int blocks = (pairs + 7) / 8;         // 4096 blocks of 8 warps

    pitch_kernel<<<blocks, 256>>>(audio, out, S, T, frames);
}

// round 2
// speedup vs baseline: 1.1540x; 1.1540x over previous
#include <cuda_runtime.h>
#include <cstdint>
#include <float.h>

#define FRAME   160
#define HOP     256
#define MIN_LAG 40
#define MAX_LAG 160
#define NBATCH  16

__device__ __forceinline__ void upk2(unsigned long long v, float& a, float& b) {
    unsigned int lo, hi;
    asm("mov.b64 {%0, %1}, %2;" : "=r"(lo), "=r"(hi) : "l"(v));
    a = __uint_as_float(lo);
    b = __uint_as_float(hi);
}
__device__ __forceinline__ unsigned long long fma2(unsigned long long a,
                                                   unsigned long long b,
                                                   unsigned long long c) {
    unsigned long long d;
    asm("fma.rn.f32x2 %0, %1, %2, %3;" : "=l"(d) : "l"(a), "l"(b), "l"(c));
    return d;
}

// One warp = two frames (A,B) interleaved as f32x2 pairs in shared memory.
// Each lane owns 4 consecutive lags l0..l0+3 (l0 = 40 + 4*tl, tl = min(lane,29)).
// Fully-unrolled sliding-window conv with circular slot indexing:
// slot(d) = d & 7 holds the f32x2 pair xpad[l0+d]. Refill lands directly in the
// vacated slots -> zero MOVs; one LDS.128 yields two ready f32x2 operands.
__global__ __launch_bounds__(256, 4)
void pitch_kernel(const float* __restrict__ audio,
                  float* __restrict__ out,
                  int S, int T, int total_frames) {
    // per-warp interleaved pair buffer: pairs [0..127] zero pad, [128..287] frame
    __shared__ __align__(16) float2 sbuf[8][288];

    const int warp = threadIdx.x >> 5;
    const int lane = threadIdx.x & 31;
    const int g0   = (blockIdx.x * 8 + warp) * 2;
    if (g0 >= total_frames) return;

    const int batch = g0 / T;
    const int f0    = g0 - batch * T;
    const float* gpA = audio + (size_t)batch * S + (size_t)f0 * HOP;
    const float* gpB = gpA + HOP;

    float2* buf = sbuf[warp];

    // ---- load both frames, mean-center, silence flags, stage interleaved ----
    float va[5], vb[5];
    #pragma unroll
    for (int i = 0; i < 5; ++i) { va[i] = gpA[lane + 32 * i]; vb[i] = gpB[lane + 32 * i]; }

    float sa = va[0] + va[1] + va[2] + va[3] + va[4];
    float sb = vb[0] + vb[1] + vb[2] + vb[3] + vb[4];
    #pragma unroll
    for (int off = 16; off; off >>= 1) {
        sa += __shfl_xor_sync(0xffffffffu, sa, off);
        sb += __shfl_xor_sync(0xffffffffu, sb, off);
    }
    const float meanA = sa / 160.0f, meanB = sb / 160.0f;

    float maA = 0.f, maB = 0.f;
    #pragma unroll
    for (int i = 0; i < 5; ++i) {
        float ca = va[i] - meanA;
        float cb = vb[i] - meanB;
        buf[128 + lane + 32 * i] = make_float2(ca, cb);   // STS.64, conflict-free
        maA = fmaxf(maA, fabsf(ca));
        maB = fmaxf(maB, fabsf(cb));
    }
    #pragma unroll
    for (int i = 0; i < 4; ++i) buf[lane + 32 * i] = make_float2(0.f, 0.f);
    #pragma unroll
    for (int off = 16; off; off >>= 1) {
        maA = fmaxf(maA, __shfl_xor_sync(0xffffffffu, maA, off));
        maB = fmaxf(maB, __shfl_xor_sync(0xffffffffu, maB, off));
    }
    __syncwarp();

    // ---- windowed self-convolution: c[l] = sum_n x[n] * xpad[l-n] ----
    const int tl = (lane < 30) ? lane : 29;
    const int l0 = MIN_LAG + 4 * tl;

    const unsigned long long* pb = (const unsigned long long*)(buf + 128);

    unsigned long long acc0 = 0ull, acc1 = 0ull, acc2 = 0ull, acc3 = 0ull;
    unsigned long long w[8];
    {   // init: slot(d)=d&7 holds pair xpad[l0+d] for d=-4..3
        ulonglong2 t0 = *(const ulonglong2*)(pb + l0 - 4);
        ulonglong2 t1 = *(const ulonglong2*)(pb + l0 - 2);
        ulonglong2 t2 = *(const ulonglong2*)(pb + l0);
        ulonglong2 t3 = *(const ulonglong2*)(pb + l0 + 2);
        w[4] = t0.x; w[5] = t0.y; w[6] = t1.x; w[7] = t1.y;
        w[0] = t2.x; w[1] = t2.y; w[2] = t3.x; w[3] = t3.y;
    }

    #pragma unroll
    for (int n0 = 0; n0 < FRAME; n0 += 4) {
        // broadcast x pairs for n0..n0+3
        const ulonglong2 xa = *(const ulonglong2*)(pb + n0);
        const ulonglong2 xb = *(const ulonglong2*)(pb + n0 + 2);
        const unsigned long long x0 = xa.x, x1 = xa.y, x2 = xb.x, x3 = xb.y;

        // acc_j += x_u * xpad[l0 + (j - n0 - u)], slot = (j-n0-u)&7
        acc0 = fma2(x0, w[(0 - n0 - 0) & 7], acc0);
        acc1 = fma2(x0, w[(1 - n0 - 0) & 7], acc1);
        acc2 = fma2(x0, w[(2 - n0 - 0) & 7], acc2);
        acc3 = fma2(x0, w[(3 - n0 - 0) & 7], acc3);
        acc0 = fma2(x1, w[(0 - n0 - 1) & 7], acc0);
        acc1 = fma2(x1, w[(1 - n0 - 1) & 7], acc1);
        acc2 = fma2(x1, w[(2 - n0 - 1) & 7], acc2);
        ac3:
        acc3 = fma2(x1, w[(3 - n0 - 1) & 7], acc3);
        acc0 = fma2(x2, w[(0 - n0 - 2) & 7], acc0);
        acc1 = fma2(x2, w[(1 - n0 - 2) & 7], acc1);
        acc2 = fma2(x2, w[(2 - n0 - 2) & 7], acc2);
        acc3 = fma2(x2, w[(3 - n0 - 2) & 7], acc3);
        acc0 = fma2(x3, w[(0 - n0 - 3) & 7], acc0);
        acc1 = fma2(x3, w[(1 - n0 - 3) & 7], acc1);
        acc2 = fma2(x3, w[(2 - n0 - 3) & 7], acc2);
        acc3 = fma2(x3, w[(3 - n0 - 3) & 7], acc3);

        // refill the 4 vacated slots with pairs xpad[l0 - n0 - 8 + k]
        if (n0 < FRAME - 4) {
            const ulonglong2 r0 = *(const ulonglong2*)(pb + l0 - n0 - 8);
            const ulonglong2 r1 = *(const ulonglong2*)(pb + l0 - n0 - 6);
            w[(0 - n0 - 8) & 7] = r0.x;
            w[(1 - n0 - 8) & 7] = r0.y;
            w[(2 - n0 - 8) & 7] = r1.x;
            w[(3 - n0 - 8) & 7] = r1.y;
        }
    }

    // ---- per-lane first-max, then warp argmax (tie -> smaller lag) ----
    float cA[4], cB[4];
    upk2(acc0, cA[0], cB[0]); upk2(acc1, cA[1], cB[1]);
    upk2(acc2, cA[2], cB[2]); upk2(acc3, cA[3], cB[3]);

    float bA = -FLT_MAX, bB = -FLT_MAX;
    int   lA = 0x7fffffff, lB = 0x7fffffff;
    if (lane < 30) {
        #pragma unroll
        for (int j = 0; j < 4; ++j) {
            const int l = l0 + j;
            if (cA[j] > bA) { bA = cA[j]; lA = l; }
            if (cB[j] > bB) { bB = cB[j]; lB = l; }
        }
    }
    #pragma unroll
    for (int off = 16; off; off >>= 1) {
        float vA = __shfl_xor_sync(0xffffffffu, bA, off);
        int   iA = __shfl_xor_sync(0xffffffffu, lA, off);
        if (vA > bA || (vA == bA && iA < lA)) { bA = vA; lA = iA; }
        float vB = __shfl_xor_sync(0xffffffffu, bB, off);
        int   iB = __shfl_xor_sync(0xffffffffu, lB, off);
        if (vB > bB || (vB == bB && iB < lB)) { bB = vB; lB = iB; }
    }

    if (lane == 0) {
        out[g0]     = (maA < 1e-8f) ? 0.f : 16000.0f / (float)lA;
        out[g0 + 1] = (maB < 1e-8f) ? 0.f : 16000.0f / (float)lB;
    }
}

extern "C" void kernel_launch(void* const* d_in, const int* in_sizes, int n_in,
                              void* d_out, int out_size) {
    const float* audio = (const float*)d_in[0];
    float* out = (float*)d_out;

    const int total = in_sizes[0];              // 16 * 1048576
    const int B = NBATCH;
    const int S = total / B;                    // 1048576
    const int T = (S - FRAME) / HOP + 1;        // 4096
    const int frames = B * T;                   // 65536 == out_size
    const int pairs  = frames / 2;              // 32768
    const int blocks = (pairs + 7) / 8;         // 4096 blocks of 8 warps

    pitch_kernel<<<blocks, 256>>>(audio, out, S, T, frames);
}

// round 3
// speedup vs baseline: 1.9385x; 1.6798x over previous
#include <cuda_runtime.h>
#include <cstdint>
#include <float.h>

#define FRAME   160
#define HOP     256
#define MIN_LAG 40
#define NBATCH  16

typedef unsigned long long ull;

__device__ __forceinline__ void upk2(ull v, float& a, float& b) {
    unsigned int lo, hi;
    asm("mov.b64 {%0, %1}, %2;" : "=r"(lo), "=r"(hi) : "l"(v));
    a = __uint_as_float(lo);
    b = __uint_as_float(hi);
}
__device__ __forceinline__ ull fma2(ull a, ull b, ull c) {
    ull d;
    asm("fma.rn.f32x2 %0, %1, %2, %3;" : "=l"(d) : "l"(a), "l"(b), "l"(c));
    return d;
}
// SW128 swizzle (Swizzle<3,4,3>) on buffer-relative byte offset; keeps 16B
// blocks intact and makes 16/32/64B lane strides conflict-free.
__device__ __forceinline__ int swz(int off) { return off ^ ((off >> 3) & 0x70); }
__device__ __forceinline__ constexpr int slot(int d) {
    int m = d % 12; return m < 0 ? m + 12 : m;
}

// One warp = FOUR frames. Buf0 holds frames (A,B) interleaved as f32x2 pairs,
// buf1 holds (C,D). Lanes 0-14 compute lags for (A,B), lanes 16-30 for (C,D);
// each lane owns 8 consecutive lags (l0 = 40 + 8*tl). 12-slot circular register
// window, slot(d) = d mod 12 (compile-time after full unroll); refills write
// directly into aging slots. All SMEM R/W swizzled -> conflict-free.
__global__ __launch_bounds__(128)
void pitch_kernel(const float* __restrict__ audio,
                  float* __restrict__ out,
                  int S, int T, int total_frames) {
    // per-warp: two pair-buffers, 384 pairs (3KB) each -> 1024B-aligned strides.
    // pairs [0..127] zero pad, [128..287] frame, [288..383] slack.
    __shared__ __align__(1024) ull sbuf[4][2][384];

    const int warp = threadIdx.x >> 5;
    const int lane = threadIdx.x & 31;
    const int g0   = (blockIdx.x * 4 + warp) * 4;   // first of 4 frames
    if (g0 >= total_frames) return;

    const int batch = g0 / T;
    const int f0    = g0 - batch * T;               // T % 4 == 0 -> same batch
    const float* base = audio + (size_t)batch * S + (size_t)f0 * HOP;

    char* b0 = (char*)sbuf[warp][0];
    char* b1 = (char*)sbuf[warp][1];

    // ---- stage 4 frames: load, mean, center, maxabs, swizzled pair store ----
    float v[4][5];
    #pragma unroll
    for (int s = 0; s < 4; ++s)
        #pragma unroll
        for (int i = 0; i < 5; ++i)
            v[s][i] = base[s * HOP + lane + 32 * i];

    float sm[4];
    #pragma unroll
    for (int s = 0; s < 4; ++s)
        sm[s] = v[s][0] + v[s][1] + v[s][2] + v[s][3] + v[s][4];
    #pragma unroll
    for (int off = 16; off; off >>= 1)
        #pragma unroll
        for (int s = 0; s < 4; ++s)
            sm[s] += __shfl_xor_sync(0xffffffffu, sm[s], off);
    float mean[4];
    #pragma unroll
    for (int s = 0; s < 4; ++s) mean[s] = sm[s] / 160.0f;

    float ma[4] = {0.f, 0.f, 0.f, 0.f};
    #pragma unroll
    for (int i = 0; i < 5; ++i) {
        float cA = v[0][i] - mean[0], cB = v[1][i] - mean[1];
        float cC = v[2][i] - mean[2], cD = v[3][i] - mean[3];
        const int off = swz(8 * (128 + lane + 32 * i));
        *(float2*)(b0 + off) = make_float2(cA, cB);
        *(float2*)(b1 + off) = make_float2(cC, cD);
        ma[0] = fmaxf(ma[0], fabsf(cA)); ma[1] = fmaxf(ma[1], fabsf(cB));
        ma[2] = fmaxf(ma[2], fabsf(cC)); ma[3] = fmaxf(ma[3], fabsf(cD));
    }
    #pragma unroll
    for (int i = 0; i < 4; ++i) {                   // zero pad pairs [0,128)
        const int off = swz(8 * (lane + 32 * i));
        *(ull*)(b0 + off) = 0ull;
        *(ull*)(b1 + off) = 0ull;
    }
    #pragma unroll
    for (int off = 16; off; off >>= 1)
        #pragma unroll
        for (int s = 0; s < 4; ++s)
            ma[s] = fmaxf(ma[s], __shfl_xor_sync(0xffffffffu, ma[s], off));
    __syncwarp();

    // ---- windowed self-conv: c[l] = sum_n x[n] * xpad[l-n], 8 lags/lane ----
    const int hl = lane & 15;
    const int tl = (hl < 15) ? hl : 14;             // lanes 15/31 duplicate
    const int l0 = MIN_LAG + 8 * tl;
    const char* mb = (lane < 16) ? b0 : b1;
    const int l0b = 8 * (128 + l0);                 // byte offset of pair l0

    ull w[12];
    #pragma unroll
    for (int k = 0; k < 6; ++k) {                   // init d = -4..7
        const ulonglong2 t = *(const ulonglong2*)(mb + swz(l0b + 8 * (2 * k - 4)));
        w[slot(-4 + 2 * k)] = t.x;
        w[slot(-3 + 2 * k)] = t.y;
    }

    ull acc[8];
    #pragma unroll
    for (int j = 0; j < 8; ++j) acc[j] = 0ull;

    #pragma unroll
    for (int n0 = 0; n0 < FRAME; n0 += 4) {
        // broadcast x pairs n0..n0+3 (uniform per half-warp, compile-time offs)
        const ulonglong2 xv0 = *(const ulonglong2*)(mb + swz(1024 + 8 * n0));
        const ulonglong2 xv1 = *(const ulonglong2*)(mb + swz(1024 + 8 * n0 + 16));
        const ull x0 = xv0.x, x1 = xv0.y, x2 = xv1.x, x3 = xv1.y;

        #pragma unroll
        for (int j = 0; j < 8; ++j) acc[j] = fma2(x0, w[slot(j - n0 - 0)], acc[j]);
        #pragma unroll
        for (int j = 0; j < 8; ++j) acc[j] = fma2(x1, w[slot(j - n0 - 1)], acc[j]);
        #pragma unroll
        for (int j = 0; j < 8; ++j) acc[j] = fma2(x2, w[slot(j - n0 - 2)], acc[j]);
        #pragma unroll
        for (int j = 0; j < 8; ++j) acc[j] = fma2(x3, w[slot(j - n0 - 3)], acc[j]);

        if (n0 < FRAME - 4) {                       // refill d = -n0-8..-n0-5
            const int r0 = l0b - 8 * n0 - 64;
            const ulonglong2 ra = *(const ulonglong2*)(mb + swz(r0));
            const ulonglong2 rb = *(const ulonglong2*)(mb + swz(r0 + 16));
            w[slot(-n0 - 8)] = ra.x;
            w[slot(-n0 - 7)] = ra.y;
            w[slot(-n0 - 6)] = rb.x;
            w[slot(-n0 - 5)] = rb.y;
        }
    }

    // ---- argmax over 8 lags/lane, then 16-lane group reduce ----
    float lo, hi;
    float bLo = -FLT_MAX, bHi = -FLT_MAX;
    int   gLo = 0x7fffffff, gHi = 0x7fffffff;
    #pragma unroll
    for (int j = 0; j < 8; ++j) {
        upk2(acc[j], lo, hi);
        const int l = l0 + j;
        if (lo > bLo) { bLo = lo; gLo = l; }
        if (hi > bHi) { bHi = hi; gHi = l; }
    }
    if (hl == 15) { bLo = -FLT_MAX; bHi = -FLT_MAX; gLo = gHi = 0x7fffffff; }

    #pragma unroll
    for (int off = 8; off; off >>= 1) {             // stays within 16-lane group
        float vL = __shfl_xor_sync(0xffffffffu, bLo, off);
        int   iL = __shfl_xor_sync(0xffffffffu, gLo, off);
        if (vL > bLo || (vL == bLo && iL < gLo)) { bLo = vL; gLo = iL; }
        float vH = __shfl_xor_sync(0xffffffffu, bHi, off);
        int   iH = __shfl_xor_sync(0xffffffffu, gHi, off);
        if (vH > bHi || (vH == bHi && iH < gHi)) { bHi = vH; gHi = iH; }
    }

    if (hl == 0) {
        const int o = g0 + ((lane >> 4) << 1);      // lane0 -> g0, lane16 -> g0+2
        const float mLo = (lane < 16) ? ma[0] : ma[2];
        const float mHi = (lane < 16) ? ma[1] : ma[3];
        out[o]     = (mLo < 1e-8f) ? 0.f : 16000.0f / (float)gLo;
        out[o + 1] = (mHi < 1e-8f) ? 0.f : 16000.0f / (float)gHi;
    }
}

extern "C" void kernel_launch(void* const* d_in, const int* in_sizes, int n_in,
                              void* d_out, int out_size) {
    const float* audio = (const float*)d_in[0];
    float* out = (float*)d_out;

    const int total = in_sizes[0];              // 16 * 1048576
    const int B = NBATCH;
    const int S = total / B;                    // 1048576
    const int T = (S - FRAME) / HOP + 1;        // 4096
    const int frames = B * T;                   // 65536 == out_size
    const int tasks  = frames / 4;              // 16384 warps
    const int blocks = (tasks + 3) / 4;         // 4096 blocks of 4 warps

    pitch_kernel<<<blocks, 128>>>(audio, out, S, T, frames);
}

// round 4
// speedup vs baseline: 1.9708x; 1.0167x over previous
#include <cuda_runtime.h>
#include <cstdint>
#include <float.h>

#define FRAME   160
#define HOP     256
#define MIN_LAG 40
#define NBATCH  16

typedef unsigned long long ull;

__device__ __forceinline__ void upk2(ull v, float& a, float& b) {
    unsigned int lo, hi;
    asm("mov.b64 {%0, %1}, %2;" : "=r"(lo), "=r"(hi) : "l"(v));
    a = __uint_as_float(lo);
    b = __uint_as_float(hi);
}
__device__ __forceinline__ ull fma2(ull a, ull b, ull c) {
    ull d;
    asm("fma.rn.f32x2 %0, %1, %2, %3;" : "=l"(d) : "l"(a), "l"(b), "l"(c));
    return d;
}
// SW128 swizzle on buffer-relative byte offset (buffers 1024B-aligned).
__device__ __forceinline__ int swz(int off) { return off ^ ((off >> 3) & 0x70); }
__device__ __forceinline__ constexpr int slot(int d) {
    int m = d % 12; return m < 0 ? m + 12 : m;
}

// One warp = 4 frames, pairs (A,B)/(C,D) interleaved as f32x2 in two buffers.
// Lanes 0-14: lags for (A,B); lanes 16-30: (C,D); 8 lags/lane, 12-slot circular
// register window. Software-pipelined: broadcast x prefetched one chunk ahead,
// refill LDS issued before the FMA block and committed after.
__global__ __launch_bounds__(128)
void pitch_kernel(const float* __restrict__ audio,
                  float* __restrict__ out,
                  int S, int T, int total_frames) {
    // per-warp: two pair-buffers of 384 pairs (3KB, 1024B-aligned strides).
    // pairs [0..127] zero pad, [128..287] frame, rest slack.
    __shared__ __align__(1024) ull sbuf[4][2][384];

    const int warp = threadIdx.x >> 5;
    const int lane = threadIdx.x & 31;
    const int g0   = (blockIdx.x * 4 + warp) * 4;
    if (g0 >= total_frames) return;

    const int batch = g0 / T;
    const int f0    = g0 - batch * T;               // T % 4 == 0 -> same batch
    const float* base = audio + (size_t)batch * S + (size_t)f0 * HOP;

    char* b0 = (char*)sbuf[warp][0];
    char* b1 = (char*)sbuf[warp][1];

    // ---- stage 4 frames: float4 loads, mean, center, maxabs, pair stores ----
    float4 q[4];
    float  t[4];
    #pragma unroll
    for (int s = 0; s < 4; ++s) {
        q[s] = ((const float4*)(base + s * HOP))[lane];     // samples 4l..4l+3
        t[s] = base[s * HOP + 128 + lane];                  // sample 128+l
    }
    float sm[4];
    #pragma unroll
    for (int s = 0; s < 4; ++s)
        sm[s] = ((q[s].x + q[s].y) + (q[s].z + q[s].w)) + t[s];
    #pragma unroll
    for (int off = 16; off; off >>= 1)
        #pragma unroll
        for (int s = 0; s < 4; ++s)
            sm[s] += __shfl_xor_sync(0xffffffffu, sm[s], off);
    float mean[4];
    #pragma unroll
    for (int s = 0; s < 4; ++s) mean[s] = sm[s] / 160.0f;

    float ma[4];
    {   // centered values; pairs at indices 4l..4l+3 via two STS.128, tail STS.64
        float cA[4], cB[4], cC[4], cD[4];
        const float* qa = &q[0].x; const float* qb = &q[1].x;
        const float* qc = &q[2].x; const float* qd = &q[3].x;
        #pragma unroll
        for (int i = 0; i < 4; ++i) {
            cA[i] = qa[i] - mean[0]; cB[i] = qb[i] - mean[1];
            cC[i] = qc[i] - mean[2]; cD[i] = qd[i] - mean[3];
        }
        const int o0 = swz(8 * (128 + 4 * lane));           // bit4 == 0
        *(float4*)(b0 + o0)        = make_float4(cA[0], cB[0], cA[1], cB[1]);
        *(float4*)(b0 + (o0 ^ 16)) = make_float4(cA[2], cB[2], cA[3], cB[3]);
        *(float4*)(b1 + o0)        = make_float4(cC[0], cD[0], cC[1], cD[1]);
        *(float4*)(b1 + (o0 ^ 16)) = make_float4(cC[2], cD[2], cC[3], cD[3]);
        const float tA = t[0] - mean[0], tB = t[1] - mean[1];
        const float tC = t[2] - mean[2], tD = t[3] - mean[3];
        const int ot = swz(8 * (256 + lane));
        *(float2*)(b0 + ot) = make_float2(tA, tB);
        *(float2*)(b1 + ot) = make_float2(tC, tD);

        ma[0] = fmaxf(fmaxf(fmaxf(fabsf(cA[0]), fabsf(cA[1])),
                            fmaxf(fabsf(cA[2]), fabsf(cA[3]))), fabsf(tA));
        ma[1] = fmaxf(fmaxf(fmaxf(fabsf(cB[0]), fabsf(cB[1])),
                            fmaxf(fabsf(cB[2]), fabsf(cB[3]))), fabsf(tB));
        ma[2] = fmaxf(fmaxf(fmaxf(fabsf(cC[0]), fabsf(cC[1])),
                            fmaxf(fabsf(cC[2]), fabsf(cC[3]))), fabsf(tC));
        ma[3] = fmaxf(fmaxf(fmaxf(fabsf(cD[0]), fabsf(cD[1])),
                            fmaxf(fabsf(cD[2]), fabsf(cD[3]))), fabsf(tD));
    }
    #pragma unroll
    for (int i = 0; i < 4; ++i) {                           // zero pad [0,128)
        const int off = swz(8 * (lane + 32 * i));
        *(ull*)(b0 + off) = 0ull;
        *(ull*)(b1 + off) = 0ull;
    }
    #pragma unroll
    for (int off = 16; off; off >>= 1)
        #pragma unroll
        for (int s = 0; s < 4; ++s)
            ma[s] = fmaxf(ma[s], __shfl_xor_sync(0xffffffffu, ma[s], off));
    __syncwarp();

    // ---- windowed self-conv: c[l] = sum_n x[n] * xpad[l-n], 8 lags/lane ----
    const int hl = lane & 15;
    const int tl = (hl < 15) ? hl : 14;
    const int l0 = MIN_LAG + 8 * tl;
    const char* mb = (lane < 16) ? b0 : b1;
    const int l0b = 8 * (128 + l0);

    ull w[12];
    {   // init d = -4..7; offsets 32-aligned -> pairwise ^16
        const int i0 = swz(l0b - 32);
        const int i1 = swz(l0b);
        const int i2 = swz(l0b + 32);
        const ulonglong2 t0 = *(const ulonglong2*)(mb + i0);
        const ulonglong2 t1 = *(const ulonglong2*)(mb + (i0 ^ 16));
        const ulonglong2 t2 = *(const ulonglong2*)(mb + i1);
        const ulonglong2 t3 = *(const ulonglong2*)(mb + (i1 ^ 16));
        const ulonglong2 t4 = *(const ulonglong2*)(mb + i2);
        const ulonglong2 t5 = *(const ulonglong2*)(mb + (i2 ^ 16));
        w[slot(-4)] = t0.x; w[slot(-3)] = t0.y;
        w[slot(-2)] = t1.x; w[slot(-1)] = t1.y;
        w[slot( 0)] = t2.x; w[slot( 1)] = t2.y;
        w[slot( 2)] = t3.x; w[slot( 3)] = t3.y;
        w[slot( 4)] = t4.x; w[slot( 5)] = t4.y;
        w[slot( 6)] = t5.x; w[slot( 7)] = t5.y;
    }

    ull acc[8];
    #pragma unroll
    for (int j = 0; j < 8; ++j) acc[j] = 0ull;

    // prefetch broadcast x for chunk 0 (offsets compile-time)
    ulonglong2 xv0 = *(const ulonglong2*)(mb + swz(1024));
    ulonglong2 xv1 = *(const ulonglong2*)(mb + (swz(1024) ^ 16));

    #pragma unroll
    for (int n0 = 0; n0 < FRAME; n0 += 4) {
        const ull x0 = xv0.x, x1 = xv0.y, x2 = xv1.x, x3 = xv1.y;

        // prefetch next chunk's broadcast (consumed next iteration)
        if (n0 < FRAME - 4) {
            const int bo = swz(1024 + 8 * (n0 + 4));        // compile-time
            xv0 = *(const ulonglong2*)(mb + bo);
            xv1 = *(const ulonglong2*)(mb + (bo ^ 16));
        }
        // issue refill loads now, commit after the FMA block
        ulonglong2 ra, rb;
        if (n0 < FRAME - 4) {
            const int r0 = swz(l0b - 8 * n0 - 64);          // bit4 == 0
            ra = *(const ulonglong2*)(mb + r0);
            rb = *(const ulonglong2*)(mb + (r0 ^ 16));
        }

        #pragma unroll
        for (int j = 0; j < 8; ++j) acc[j] = fma2(x0, w[slot(j - n0 - 0)], acc[j]);
        #pragma unroll
        for (int j = 0; j < 8; ++j) acc[j] = fma2(x1, w[slot(j - n0 - 1)], acc[j]);
        #pragma unroll
        for (int j = 0; j < 8; ++j) acc[j] = fma2(x2, w[slot(j - n0 - 2)], acc[j]);
        #pragma unroll
        for (int j = 0; j < 8; ++j) acc[j] = fma2(x3, w[slot(j - n0 - 3)], acc[j]);

        if (n0 < FRAME - 4) {                               // commit refills
            w[slot(-n0 - 8)] = ra.x;
            w[slot(-n0 - 7)] = ra.y;
            w[slot(-n0 - 6)] = rb.x;
            w[slot(-n0 - 5)] = rb.y;
        }
    }

    // ---- argmax over 8 lags/lane, then 16-lane group reduce ----
    float lo, hi;
    float bLo = -FLT_MAX, bHi = -FLT_MAX;
    int   gLo = 0x7fffffff, gHi = 0x7fffffff;
    #pragma unroll
    for (int j = 0; j < 8; ++j) {
        upk2(acc[j], lo, hi);
        const int l = l0 + j;
        if (lo > bLo) { bLo = lo; gLo = l; }
        if (hi > bHi) { bHi = hi; gHi = l; }
    }
    if (hl == 15) { bLo = -FLT_MAX; bHi = -FLT_MAX; gLo = gHi = 0x7fffffff; }

    #pragma unroll
    for (int off = 8; off; off >>= 1) {                     // within 16-lane group
        float vL = __shfl_xor_sync(0xffffffffu, bLo, off);
        int   iL = __shfl_xor_sync(0xffffffffu, gLo, off);
        if (vL > bLo || (vL == bLo && iL < gLo)) { bLo = vL; gLo = iL; }
        float vH = __shfl_xor_sync(0xffffffffu, bHi, off);
        int   iH = __shfl_xor_sync(0xffffffffu, gHi, off);
        if (vH > bHi || (vH == bHi && iH < gHi)) { bHi = vH; gHi = iH; }
    }

    if (hl == 0) {
        const int o = g0 + ((lane >> 4) << 1);
        const float mLo = (lane < 16) ? ma[0] : ma[2];
        const float mHi = (lane < 16) ? ma[1] : ma[3];
        out[o]     = (mLo < 1e-8f) ? 0.f : 16000.0f / (float)gLo;
        out[o + 1] = (mHi < 1e-8f) ? 0.f : 16000.0f / (float)gHi;
    }
}

extern "C" void kernel_launch(void* const* d_in, const int* in_sizes, int n_in,
                              void* d_out, int out_size) {
    const float* audio = (const float*)d_in[0];
    float* out = (float*)d_out;

    const int total = in_sizes[0];              // 16 * 1048576
    const int B = NBATCH;
    const int S = total / B;                    // 1048576
    const int T = (S - FRAME) / HOP + 1;        // 4096
    const int frames = B * T;                   // 65536 == out_size
    const int tasks  = frames / 4;              // 16384 warps
    const int blocks = (tasks + 3) / 4;         // 4096 blocks of 4 warps

    pitch_kernel<<<blocks, 128>>>(audio, out, S, T, frames);
}

// round 8
// speedup vs baseline: 2.0011x; 1.0153x over previous
#include <cuda_runtime.h>
#include <cstdint>
#include <float.h>

#define FRAME   160
#define HOP     256
#define MIN_LAG 40
#define NBATCH  16

typedef unsigned long long ull;

__device__ __forceinline__ void upk2(ull v, float& a, float& b) {
    unsigned int lo, hi;
    asm("mov.b64 {%0, %1}, %2;" : "=r"(lo), "=r"(hi) : "l"(v));
    a = __uint_as_float(lo);
    b = __uint_as_float(hi);
}
__device__ __forceinline__ ull fma2(ull a, ull b, ull c) {
    ull d;
    asm("fma.rn.f32x2 %0, %1, %2, %3;" : "=l"(d) : "l"(a), "l"(b), "l"(c));
    return d;
}
// SW128 swizzle on buffer-relative byte offset (buffers 1024B-aligned).
// off ^ ((off>>3)&0x70) == one SHF + one LOP3 at runtime.
__device__ __forceinline__ int swz(int off) { return off ^ ((off >> 3) & 0x70); }
__device__ __forceinline__ constexpr int slot(int d) {
    int m = d % 12; return m < 0 ? m + 12 : m;
}

// One warp = 4 frames, pairs (A,B)/(C,D) interleaved as f32x2 in two buffers.
// Lanes 0-14: lags for (A,B); lanes 16-30: (C,D); 8 lags/lane, 12-slot circular
// register window. ROLLED loop: 13 macro-iters x 3 chunks (slot period 12)
// + 1 epilogue chunk -> ~2.4KB hot body fits L0 I$ (the R4 full unroll was
// ~32KB and streamed from L2-I$ every iteration).
__global__ __launch_bounds__(128)
void pitch_kernel(const float* __restrict__ audio,
                  float* __restrict__ out,
                  int S, int T, int total_frames) {
    // per-warp: two pair-buffers of 384 pairs (3KB, 1024B-aligned strides).
    // pairs [0..127] zero pad, [128..287] frame, rest slack.
    __shared__ __align__(1024) ull sbuf[4][2][384];

    const int warp = threadIdx.x >> 5;
    const int lane = threadIdx.x & 31;
    const int g0   = (blockIdx.x * 4 + warp) * 4;
    if (g0 >= total_frames) return;

    const int batch = g0 / T;
    const int f0    = g0 - batch * T;               // T % 4 == 0 -> same batch
    const float* base = audio + (size_t)batch * S + (size_t)f0 * HOP;

    char* b0 = (char*)sbuf[warp][0];
    char* b1 = (char*)sbuf[warp][1];

    // ---- stage 4 frames: float4 loads, mean, center, maxabs, pair stores ----
    float4 q[4];
    float  t[4];
    #pragma unroll
    for (int s = 0; s < 4; ++s) {
        q[s] = ((const float4*)(base + s * HOP))[lane];     // samples 4l..4l+3
        t[s] = base[s * HOP + 128 + lane];                  // sample 128+l
    }
    float sm[4];
    #pragma unroll
    for (int s = 0; s < 4; ++s)
        sm[s] = ((q[s].x + q[s].y) + (q[s].z + q[s].w)) + t[s];
    #pragma unroll
    for (int off = 16; off; off >>= 1)
        #pragma unroll
        for (int s = 0; s < 4; ++s)
            sm[s] += __shfl_xor_sync(0xffffffffu, sm[s], off);
    float mean[4];
    #pragma unroll
    for (int s = 0; s < 4; ++s) mean[s] = sm[s] / 160.0f;

    float ma[4];
    {   // centered values; pairs 4l..4l+3 via two STS.128 each, tail STS.64
        float cA[4], cB[4], cC[4], cD[4];
        const float* qa = &q[0].x; const float* qb = &q[1].x;
        const float* qc = &q[2].x; const float* qd = &q[3].x;
        #pragma unroll
        for (int i = 0; i < 4; ++i) {
            cA[i] = qa[i] - mean[0]; cB[i] = qb[i] - mean[1];
            cC[i] = qc[i] - mean[2]; cD[i] = qd[i] - mean[3];
        }
        const int o0 = swz(8 * (128 + 4 * lane));           // bit4 == 0
        *(float4*)(b0 + o0)        = make_float4(cA[0], cB[0], cA[1], cB[1]);
        *(float4*)(b0 + (o0 ^ 16)) = make_float4(cA[2], cB[2], cA[3], cB[3]);
        *(float4*)(b1 + o0)        = make_float4(cC[0], cD[0], cC[1], cD[1]);
        *(float4*)(b1 + (o0 ^ 16)) = make_float4(cC[2], cD[2], cC[3], cD[3]);
        const float tA = t[0] - mean[0], tB = t[1] - mean[1];
        const float tC = t[2] - mean[2], tD = t[3] - mean[3];
        const int ot = swz(8 * (256 + lane));
        *(float2*)(b0 + ot) = make_float2(tA, tB);
        *(float2*)(b1 + ot) = make_float2(tC, tD);

        ma[0] = fmaxf(fmaxf(fmaxf(fabsf(cA[0]), fabsf(cA[1])),
                            fmaxf(fabsf(cA[2]), fabsf(cA[3]))), fabsf(tA));
        ma[1] = fmaxf(fmaxf(fmaxf(fabsf(cB[0]), fabsf(cB[1])),
                            fmaxf(fabsf(cB[2]), fabsf(cB[3]))), fabsf(tB));
        ma[2] = fmaxf(fmaxf(fmaxf(fabsf(cC[0]), fabsf(cC[1])),
                            fmaxf(fabsf(cC[2]), fabsf(cC[3]))), fabsf(tC));
        ma[3] = fmaxf(fmaxf(fmaxf(fabsf(cD[0]), fabsf(cD[1])),
                            fmaxf(fabsf(cD[2]), fabsf(cD[3]))), fabsf(tD));
    }
    #pragma unroll
    for (int i = 0; i < 4; ++i) {                           // zero pad [0,128)
        const int off = swz(8 * (lane + 32 * i));
        *(ull*)(b0 + off) = 0ull;
        *(ull*)(b1 + off) = 0ull;
    }
    #pragma unroll
    for (int off = 16; off; off >>= 1)
        #pragma unroll
        for (int s = 0; s < 4; ++s)
            ma[s] = fmaxf(ma[s], __shfl_xor_sync(0xffffffffu, ma[s], off));
    __syncwarp();

    // ---- windowed self-conv: c[l] = sum_n x[n] * xpad[l-n], 8 lags/lane ----
    const int hl = lane & 15;
    const int tl = (hl < 15) ? hl : 14;
    const int l0 = MIN_LAG + 8 * tl;
    const char* mb = (lane < 16) ? b0 : b1;
    const int l0b = 8 * (128 + l0);

    ull w[12];
    {   // init d = -4..7; offsets 32-aligned -> pairwise ^16
        const int i0 = swz(l0b - 32);
        const int i1 = swz(l0b);
        const int i2 = swz(l0b + 32);
        const ulonglong2 t0 = *(const ulonglong2*)(mb + i0);
        const ulonglong2 t1 = *(const ulonglong2*)(mb + (i0 ^ 16));
        const ulonglong2 t2 = *(const ulonglong2*)(mb + i1);
        const ulonglong2 t3 = *(const ulonglong2*)(mb + (i1 ^ 16));
        const ulonglong2 t4 = *(const ulonglong2*)(mb + i2);
        const ulonglong2 t5 = *(const ulonglong2*)(mb + (i2 ^ 16));
        w[slot(-4)] = t0.x; w[slot(-3)] = t0.y;
        w[slot(-2)] = t1.x; w[slot(-1)] = t1.y;
        w[slot( 0)] = t2.x; w[slot( 1)] = t2.y;
        w[slot( 2)] = t3.x; w[slot( 3)] = t3.y;
        w[slot( 4)] = t4.x; w[slot( 5)] = t4.y;
        w[slot( 6)] = t5.x; w[slot( 7)] = t5.y;
    }

    ull acc[8];
    #pragma unroll
    for (int j = 0; j < 8; ++j) acc[j] = 0ull;

    // prefetch broadcast x for chunk 0 (compile-time offsets)
    ulonglong2 xv0 = *(const ulonglong2*)(mb + swz(1024));
    ulonglong2 xv1 = *(const ulonglong2*)(mb + (swz(1024) ^ 16));

    int bro = 1024 + 32;        // raw byte off of broadcast pairs for n = 4
    int rro = l0b - 64;         // raw byte off of refill pairs for chunk n = 0

    // One chunk; C = (n/4) % 3 selects the compile-time slot pattern.
    // PRE: prefetch next chunk's broadcast.  REF: load+commit window refill.
#define DO_CHUNK(C, PRE, REF)                                                 \
    {                                                                         \
        const ull x0 = xv0.x, x1 = xv0.y, x2 = xv1.x, x3 = xv1.y;             \
        if (PRE) {                                                            \
            const int bo = swz(bro);                                          \
            xv0 = *(const ulonglong2*)(mb + bo);                              \
            xv1 = *(const ulonglong2*)(mb + (bo ^ 16));                       \
            bro += 32;                                                        \
        }                                                                     \
        ulonglong2 ra, rb;                                                    \
        if (REF) {                                                            \
            const int r0 = swz(rro);                                          \
            ra = *(const ulonglong2*)(mb + r0);                               \
            rb = *(const ulonglong2*)(mb + (r0 ^ 16));                        \
            rro -= 32;                                                        \
        }                                                                     \
        _Pragma("unroll")                                                     \
        for (int j = 0; j < 8; ++j)                                           \
            acc[j] = fma2(x0, w[slot(j - 4 * (C) - 0)], acc[j]);              \
        _Pragma("unroll")                                                     \
        for (int j = 0; j < 8; ++j)                                           \
            acc[j] = fma2(x1, w[slot(j - 4 * (C) - 1)], acc[j]);              \
        _Pragma("unroll")                                                     \
        for (int j = 0; j < 8; ++j)                                           \
            acc[j] = fma2(x2, w[slot(j - 4 * (C) - 2)], acc[j]);              \
        _Pragma("unroll")                                                     \
        for (int j = 0; j < 8; ++j)                                           \
            acc[j] = fma2(x3, w[slot(j - 4 * (C) - 3)], acc[j]);              \
        if (REF) {                                                            \
            w[slot(-4 * (C) - 8)] = ra.x;                                     \
            w[slot(-4 * (C) - 7)] = ra.y;                                     \
            w[slot(-4 * (C) - 6)] = rb.x;                                     \
            w[slot(-4 * (C) - 5)] = rb.y;                                     \
        }                                                                     \
    }

    #pragma unroll 1
    for (int it = 0; it < 13; ++it) {       // n = 12*it + {0,4,8}
        DO_CHUNK(0, true, true)
        DO_CHUNK(1, true, true)
        DO_CHUNK(2, true, true)
    }
    DO_CHUNK(0, false, false)               // n = 156 (156 % 12 == 0)
#undef DO_CHUNK

    // ---- argmax over 8 lags/lane, then 16-lane group reduce ----
    float lo, hi;
    float bLo = -FLT_MAX, bHi = -FLT_MAX;
    int   gLo = 0x7fffffff, gHi = 0x7fffffff;
    #pragma unroll
    for (int j = 0; j < 8; ++j) {
        upk2(acc[j], lo, hi);
        const int l = l0 + j;
        if (lo > bLo) { bLo = lo; gLo = l; }
        if (hi > bHi) { bHi = hi; gHi = l; }
    }
    if (hl == 15) { bLo = -FLT_MAX; bHi = -FLT_MAX; gLo = gHi = 0x7fffffff; }

    #pragma unroll
    for (int off = 8; off; off >>= 1) {                     // within 16-lane group
        float vL = __shfl_xor_sync(0xffffffffu, bLo, off);
        int   iL = __shfl_xor_sync(0xffffffffu, gLo, off);
        if (vL > bLo || (vL == bLo && iL < gLo)) { bLo = vL; gLo = iL; }
        float vH = __shfl_xor_sync(0xffffffffu, bHi, off);
        int   iH = __shfl_xor_sync(0xffffffffu, gHi, off);
        if (vH > bHi || (vH == bHi && iH < gHi)) { bHi = vH; gHi = iH; }
    }

    if (hl == 0) {
        const int o = g0 + ((lane >> 4) << 1);
        const float mLo = (lane < 16) ? ma[0] : ma[2];
        const float mHi = (lane < 16) ? ma[1] : ma[3];
        out[o]     = (mLo < 1e-8f) ? 0.f : 16000.0f / (float)gLo;
        out[o + 1] = (mHi < 1e-8f) ? 0.f : 16000.0f / (float)gHi;
    }
}

extern "C" void kernel_launch(void* const* d_in, const int* in_sizes, int n_in,
                              void* d_out, int out_size) {
    const float* audio = (const float*)d_in[0];
    float* out = (float*)d_out;

    const int total = in_sizes[0];              // 16 * 1048576
    const int B = NBATCH;
    const int S = total / B;                    // 1048576
    const int T = (S - FRAME) / HOP + 1;        // 4096
    const int frames = B * T;                   // 65536 == out_size
    const int tasks  = frames / 4;              // 16384 warps
    const int blocks = (tasks + 3) / 4;         // 4096 blocks of 4 warps

    pitch_kernel<<<blocks, 128>>>(audio, out, S, T, frames);
}

// round 10
// speedup vs baseline: 2.9220x; 1.4602x over previous
#include <cuda_runtime.h>
#include <cstdint>
#include <float.h>

#define FRAME   160
#define HOP     256
#define MIN_LAG 40
#define NBATCH  16

typedef unsigned long long ull;

__device__ __forceinline__ void upk2(ull v, float& a, float& b) {
    unsigned int lo, hi;
    asm("mov.b64 {%0, %1}, %2;" : "=r"(lo), "=r"(hi) : "l"(v));
    a = __uint_as_float(lo);
    b = __uint_as_float(hi);
}
__device__ __forceinline__ ull fma2(ull a, ull b, ull c) {
    ull d;
    asm("fma.rn.f32x2 %0, %1, %2, %3;" : "=l"(d) : "l"(a), "l"(b), "l"(c));
    return d;
}
__device__ __forceinline__ ull mul2(ull a, ull b) {
    ull d;
    asm("mul.rn.f32x2 %0, %1, %2;" : "=l"(d) : "l"(a), "l"(b));
    return d;
}
// SW128 swizzle on buffer-relative byte offset (buffers 1024B-aligned).
__device__ __forceinline__ int swz(int off) { return off ^ ((off >> 3) & 0x70); }
__device__ __forceinline__ constexpr int slot(int d) {
    int m = d % 12; return m < 0 ? m + 12 : m;
}

// FOLDED self-convolution: c[l] = 2*sum_{n<ceil(l/2)} x[n]x[l-n] + [l even]x[l/2]^2.
// We accumulate half-sum + 1/2*center; argmax is invariant under the final x2.
// Per lane (lags l0..l0+7, l0 even): stops s_j = h0+u_j, h0 = l0/2 = 20+4*tl
// (multiple of 4!), u = [0,1,1,2,2,3,3,4]. Common loop: 19 uniform chunks with
// per-lane chunk masking (sign-mask AND on broadcast x; whole chunks valid or
// void). Boundary chunk (n = h0..h0+3): lane-invariant compile-time pattern.
__global__ __launch_bounds__(128)
void pitch_kernel(const float* __restrict__ audio,
                  float* __restrict__ out,
                  int S, int T, int total_frames) {
    // per-warp: two pair-buffers of 384 pairs (3KB, 1024B-aligned strides).
    // pairs [0..127] zero pad, [128..287] frame, rest slack.
    __shared__ __align__(1024) ull sbuf[4][2][384];

    const int warp = threadIdx.x >> 5;
    const int lane = threadIdx.x & 31;
    const int g0   = (blockIdx.x * 4 + warp) * 4;
    if (g0 >= total_frames) return;

    const int batch = g0 / T;
    const int f0    = g0 - batch * T;               // T % 4 == 0 -> same batch
    const float* base = audio + (size_t)batch * S + (size_t)f0 * HOP;

    char* b0 = (char*)sbuf[warp][0];
    char* b1 = (char*)sbuf[warp][1];

    // ---- stage 4 frames: float4 loads, mean, center, maxabs, pair stores ----
    float4 q[4];
    float  t[4];
    #pragma unroll
    for (int s = 0; s < 4; ++s) {
        q[s] = ((const float4*)(base + s * HOP))[lane];     // samples 4l..4l+3
        t[s] = base[s * HOP + 128 + lane];                  // sample 128+l
    }
    float sm[4];
    #pragma unroll
    for (int s = 0; s < 4; ++s)
        sm[s] = ((q[s].x + q[s].y) + (q[s].z + q[s].w)) + t[s];
    #pragma unroll
    for (int off = 16; off; off >>= 1)
        #pragma unroll
        for (int s = 0; s < 4; ++s)
            sm[s] += __shfl_xor_sync(0xffffffffu, sm[s], off);
    float mean[4];
    #pragma unroll
    for (int s = 0; s < 4; ++s) mean[s] = sm[s] / 160.0f;

    float ma[4];
    {   // centered values; pairs 4l..4l+3 via two STS.128 each, tail STS.64
        float cA[4], cB[4], cC[4], cD[4];
        const float* qa = &q[0].x; const float* qb = &q[1].x;
        const float* qc = &q[2].x; const float* qd = &q[3].x;
        #pragma unroll
        for (int i = 0; i < 4; ++i) {
            cA[i] = qa[i] - mean[0]; cB[i] = qb[i] - mean[1];
            cC[i] = qc[i] - mean[2]; cD[i] = qd[i] - mean[3];
        }
        const int o0 = swz(8 * (128 + 4 * lane));           // bit4 == 0
        *(float4*)(b0 + o0)        = make_float4(cA[0], cB[0], cA[1], cB[1]);
        *(float4*)(b0 + (o0 ^ 16)) = make_float4(cA[2], cB[2], cA[3], cB[3]);
        *(float4*)(b1 + o0)        = make_float4(cC[0], cD[0], cC[1], cD[1]);
        *(float4*)(b1 + (o0 ^ 16)) = make_float4(cC[2], cD[2], cC[3], cD[3]);
        const float tA = t[0] - mean[0], tB = t[1] - mean[1];
        const float tC = t[2] - mean[2], tD = t[3] - mean[3];
        const int ot = swz(8 * (256 + lane));
        *(float2*)(b0 + ot) = make_float2(tA, tB);
        *(float2*)(b1 + ot) = make_float2(tC, tD);

        ma[0] = fmaxf(fmaxf(fmaxf(fabsf(cA[0]), fabsf(cA[1])),
                            fmaxf(fabsf(cA[2]), fabsf(cA[3]))), fabsf(tA));
        ma[1] = fmaxf(fmaxf(fmaxf(fabsf(cB[0]), fabsf(cB[1])),
                            fmaxf(fabsf(cB[2]), fabsf(cB[3]))), fabsf(tB));
        ma[2] = fmaxf(fmaxf(fmaxf(fabsf(cC[0]), fabsf(cC[1])),
                            fmaxf(fabsf(cC[2]), fabsf(cC[3]))), fabsf(tC));
        ma[3] = fmaxf(fmaxf(fmaxf(fabsf(cD[0]), fabsf(cD[1])),
                            fmaxf(fabsf(cD[2]), fabsf(cD[3]))), fabsf(tD));
    }
    #pragma unroll
    for (int i = 0; i < 4; ++i) {                           // zero pad [0,128)
        const int off = swz(8 * (lane + 32 * i));
        *(ull*)(b0 + off) = 0ull;
        *(ull*)(b1 + off) = 0ull;
    }
    #pragma unroll
    for (int off = 16; off; off >>= 1)
        #pragma unroll
        for (int s = 0; s < 4; ++s)
            ma[s] = fmaxf(ma[s], __shfl_xor_sync(0xffffffffu, ma[s], off));
    __syncwarp();

    // ---- folded windowed self-conv, 8 lags/lane ----
    const int hl = lane & 15;
    const int tl = (hl < 15) ? hl : 14;
    const int l0 = MIN_LAG + 8 * tl;
    const int h0 = l0 >> 1;                                 // 20 + 4*tl
    const char* mb = (lane < 16) ? b0 : b1;
    const int l0b = 8 * (128 + l0);

    ull w[12];
    {   // init d = -4..7; offsets 32-aligned -> pairwise ^16
        const int i0 = swz(l0b - 32);
        const int i1 = swz(l0b);
        const int i2 = swz(l0b + 32);
        const ulonglong2 t0 = *(const ulonglong2*)(mb + i0);
        const ulonglong2 t1 = *(const ulonglong2*)(mb + (i0 ^ 16));
        const ulonglong2 t2 = *(const ulonglong2*)(mb + i1);
        const ulonglong2 t3 = *(const ulonglong2*)(mb + (i1 ^ 16));
        const ulonglong2 t4 = *(const ulonglong2*)(mb + i2);
        const ulonglong2 t5 = *(const ulonglong2*)(mb + (i2 ^ 16));
        w[slot(-4)] = t0.x; w[slot(-3)] = t0.y;
        w[slot(-2)] = t1.x; w[slot(-1)] = t1.y;
        w[slot( 0)] = t2.x; w[slot( 1)] = t2.y;
        w[slot( 2)] = t3.x; w[slot( 3)] = t3.y;
        w[slot( 4)] = t4.x; w[slot( 5)] = t4.y;
        w[slot( 6)] = t5.x; w[slot( 7)] = t5.y;
    }

    ull acc[8];
    #pragma unroll
    for (int j = 0; j < 8; ++j) acc[j] = 0ull;

    // prefetch broadcast x for chunk 0
    ulonglong2 xv0 = *(const ulonglong2*)(mb + swz(1024));
    ulonglong2 xv1 = *(const ulonglong2*)(mb + (swz(1024) ^ 16));

    int bro = 1024 + 32;        // raw byte off of broadcast pairs for n = 4
    int rro = l0b - 64;         // raw byte off of refill pairs for chunk n = 0
    int cnt = -h0;              // n0 - h0; chunk active iff cnt < 0

    // One chunk; C = (n0/4) % 3 selects compile-time slot pattern.
    // Broadcast x is AND-masked to zero for lanes past their fold point h0.
#define DO_CHUNK(C, PRE, REF)                                                 \
    {                                                                         \
        const unsigned m32 = (unsigned)(cnt >> 31);                           \
        cnt += 4;                                                             \
        const ull mm = ((ull)m32 << 32) | m32;                                \
        const ull x0 = xv0.x & mm, x1 = xv0.y & mm;                           \
        const ull x2 = xv1.x & mm, x3 = xv1.y & mm;                           \
        if (PRE) {                                                            \
            const int bo = swz(bro);                                          \
            xv0 = *(const ulonglong2*)(mb + bo);                              \
            xv1 = *(const ulonglong2*)(mb + (bo ^ 16));                       \
            bro += 32;                                                        \
        }                                                                     \
        ulonglong2 ra, rb;                                                    \
        if (REF) {                                                            \
            const int r0 = swz(rro);                                          \
            ra = *(const ulonglong2*)(mb + r0);                               \
            rb = *(const ulonglong2*)(mb + (r0 ^ 16));                        \
            rro -= 32;                                                        \
        }                                                                     \
        _Pragma("unroll")                                                     \
        for (int j = 0; j < 8; ++j)                                           \
            acc[j] = fma2(x0, w[slot(j - 4 * (C) - 0)], acc[j]);              \
        _Pragma("unroll")                                                     \
        for (int j = 0; j < 8; ++j)                                           \
            acc[j] = fma2(x1, w[slot(j - 4 * (C) - 1)], acc[j]);              \
        _Pragma("unroll")                                                     \
        for (int j = 0; j < 8; ++j)                                           \
            acc[j] = fma2(x2, w[slot(j - 4 * (C) - 2)], acc[j]);              \
        _Pragma("unroll")                                                     \
        for (int j = 0; j < 8; ++j)                                           \
            acc[j] = fma2(x3, w[slot(j - 4 * (C) - 3)], acc[j]);              \
        if (REF) {                                                            \
            w[slot(-4 * (C) - 8)] = ra.x;                                     \
            w[slot(-4 * (C) - 7)] = ra.y;                                     \
            w[slot(-4 * (C) - 6)] = rb.x;                                     \
            w[slot(-4 * (C) - 5)] = rb.y;                                     \
        }                                                                     \
    }

    #pragma unroll 1
    for (int it = 0; it < 6; ++it) {        // n0 = 12*it + {0,4,8}  (0..68)
        DO_CHUNK(0, true, true)
        DO_CHUNK(1, true, true)
        DO_CHUNK(2, true, true)
    }
    DO_CHUNK(0, false, false)               // n0 = 72 (72 % 12 == 0)
#undef DO_CHUNK

    // ---- boundary chunk: n = h0..h0+3, strict tail + half-centers ----
    // acc_j += x[h0+e] * x[h0+j-e] for e < u_j (u=[0,1,1,2,2,3,3,4]);
    // acc_j += 0.5*x[h0+j/2]^2 for even j.  v[k] = pair x[h0-4+k], k=0..11.
    {
        const int bo = 8 * (128 + h0);                      // 32-aligned
        const int o1 = swz(bo - 32);
        const int o2 = swz(bo);
        const int o3 = swz(bo + 32);
        const ulonglong2 p0 = *(const ulonglong2*)(mb + o1);
        const ulonglong2 p1 = *(const ulonglong2*)(mb + (o1 ^ 16));
        const ulonglong2 p2 = *(const ulonglong2*)(mb + o2);
        const ulonglong2 p3 = *(const ulonglong2*)(mb + (o2 ^ 16));
        const ulonglong2 p4 = *(const ulonglong2*)(mb + o3);
        const ulonglong2 p5 = *(const ulonglong2*)(mb + (o3 ^ 16));
        const ull v4 = p2.x, v5 = p2.y, v6 = p3.x, v7 = p3.y;
        const ull v8 = p4.x, v9 = p4.y, v10 = p5.x, v11 = p5.y;
        (void)p0; (void)p1;                                  // pairs h0-4..h0-1 unused

        const ull HALF2 = 0x3F0000003F000000ull;            // packed (0.5f, 0.5f)
        const ull h4 = mul2(v4, HALF2);
        const ull h5 = mul2(v5, HALF2);
        const ull h6 = mul2(v6, HALF2);
        const ull h7 = mul2(v7, HALF2);

        // e = 0 (x = v4)
        acc[0] = fma2(h4, v4,  acc[0]);                     // center l0+0
        acc[1] = fma2(v4, v5,  acc[1]);
        acc[2] = fma2(v4, v6,  acc[2]);
        acc[3] = fma2(v4, v7,  acc[3]);
        acc[4] = fma2(v4, v8,  acc[4]);
        acc[5] = fma2(v4, v9,  acc[5]);
        acc[6] = fma2(v4, v10, acc[6]);
        acc[7] = fma2(v4, v11, acc[7]);
        // e = 1 (x = v5)
        acc[2] = fma2(h5, v5,  acc[2]);                     // center l0+2
        acc[3] = fma2(v5, v6,  acc[3]);
        acc[4] = fma2(v5, v7,  acc[4]);
        acc[5] = fma2(v5, v8,  acc[5]);
        acc[6] = fma2(v5, v9,  acc[6]);
        acc[7] = fma2(v5, v10, acc[7]);
        // e = 2 (x = v6)
        acc[4] = fma2(h6, v6,  acc[4]);                     // center l0+4
        acc[5] = fma2(v6, v7,  acc[5]);
        acc[6] = fma2(v6, v8,  acc[6]);
        acc[7] = fma2(v6, v9,  acc[7]);
        // e = 3 (x = v7)
        acc[6] = fma2(h7, v7,  acc[6]);                     // center l0+6
        acc[7] = fma2(v7, v8,  acc[7]);
    }

    // ---- argmax over 8 lags/lane, then 16-lane group reduce ----
    // acc == c[l]/2 exactly up to rounding; argmax invariant under x2.
    float lo, hi;
    float bLo = -FLT_MAX, bHi = -FLT_MAX;
    int   gLo = 0x7fffffff, gHi = 0x7fffffff;
    #pragma unroll
    for (int j = 0; j < 8; ++j) {
        upk2(acc[j], lo, hi);
        const int l = l0 + j;
        if (lo > bLo) { bLo = lo; gLo = l; }
        if (hi > bHi) { bHi = hi; gHi = l; }
    }
    if (hl == 15) { bLo = -FLT_MAX; bHi = -FLT_MAX; gLo = gHi = 0x7fffffff; }

    #pragma unroll
    for (int off = 8; off; off >>= 1) {                     // within 16-lane group
        float vL = __shfl_xor_sync(0xffffffffu, bLo, off);
        int   iL = __shfl_xor_sync(0xffffffffu, gLo, off);
        if (vL > bLo || (vL == bLo && iL < gLo)) { bLo = vL; gLo = iL; }
        float vH = __shfl_xor_sync(0xffffffffu, bHi, off);
        int   iH = __shfl_xor_sync(0xffffffffu, gHi, off);
        if (vH > bHi || (vH == bHi && iH < gHi)) { bHi = vH; gHi = iH; }
    }

    if (hl == 0) {
        const int o = g0 + ((lane >> 4) << 1);
        const float mLo = (lane < 16) ? ma[0] : ma[2];
        const float mHi = (lane < 16) ? ma[1] : ma[3];
        out[o]     = (mLo < 1e-8f) ? 0.f : 16000.0f / (float)gLo;
        out[o + 1] = (mHi < 1e-8f) ? 0.f : 16000.0f / (float)gHi;
    }
}

extern "C" void kernel_launch(void* const* d_in, const int* in_sizes, int n_in,
                              void* d_out, int out_size) {
    const float* audio = (const float*)d_in[0];
    float* out = (float*)d_out;

    const int total = in_sizes[0];              // 16 * 1048576
    const int B = NBATCH;
    const int S = total / B;                    // 1048576
    const int T = (S - FRAME) / HOP + 1;        // 4096
    const int frames = B * T;                   // 65536 == out_size
    const int tasks  = frames / 4;              // 16384 warps
    const int blocks = (tasks + 3) / 4;         // 4096 blocks of 4 warps

    pitch_kernel<<<blocks, 128>>>(audio, out, S, T, frames);
}